// round 3
// baseline (speedup 1.0000x reference)
#include <cuda_runtime.h>
#include <cuda_bf16.h>
#include <math_constants.h>

#define B_   16
#define C_   256
#define N_   4096
#define O3_  768
#define HEADS_ 8
#define HD_  32
#define EPS_ 1e-5f

__device__ float g_qkv[(size_t)B_ * O3_ * N_];
__device__ float g_ctx[(size_t)B_ * HEADS_ * HD_ * HD_];
__device__ float g_M[(size_t)B_ * C_ * C_];

// ---------------------------------------------------------------------------
// Double-buffered 128x128x16 SGEMM with per-output-channel BN epilogue.
// C[o,n] = BN( sum_c A[o,c] * Bm[c,n] )   per batch (blockIdx.z)
// ---------------------------------------------------------------------------
__global__ __launch_bounds__(256, 2)
void gemm128_bn(const float* __restrict__ A, long aStride,
                const float* __restrict__ Bm, long bStride,
                float* __restrict__ Out, long oStride,
                const float* __restrict__ gamma, const float* __restrict__ beta,
                const float* __restrict__ mean,  const float* __restrict__ var)
{
    const int b  = blockIdx.z;
    const int n0 = blockIdx.x * 128;
    const int o0 = blockIdx.y * 128;
    const float* Ab = A  + (size_t)b * aStride;
    const float* Bb = Bm + (size_t)b * bStride;
    float*       Ob = Out + (size_t)b * oStride;

    __shared__ float As[2][16][128];
    __shared__ float Bs[2][16][128];

    const int t  = threadIdx.x;
    const int ty = t >> 4;
    const int tx = t & 15;

    float acc[8][8];
#pragma unroll
    for (int i = 0; i < 8; i++)
#pragma unroll
        for (int j = 0; j < 8; j++) acc[i][j] = 0.f;

    const int ra = t >> 2;            // 0..63
    const int ca = (t & 3) * 4;       // 0,4,8,12
    const int rb = t >> 5;            // 0..7
    const int cb = (t & 31) * 4;      // 0..124

    float4 pa[2], pb[2];

    // prefetch k0=0 to regs
#pragma unroll
    for (int rr = 0; rr < 2; rr++) {
        pa[rr] = *(const float4*)&Ab[(size_t)(o0 + ra + rr * 64) * 256 + 0 + ca];
        pb[rr] = *(const float4*)&Bb[(size_t)(0 + rb + rr * 8) * N_ + n0 + cb];
    }
    // store to buf 0
#pragma unroll
    for (int rr = 0; rr < 2; rr++) {
        As[0][ca + 0][ra + rr * 64] = pa[rr].x;
        As[0][ca + 1][ra + rr * 64] = pa[rr].y;
        As[0][ca + 2][ra + rr * 64] = pa[rr].z;
        As[0][ca + 3][ra + rr * 64] = pa[rr].w;
        *(float4*)&Bs[0][rb + rr * 8][cb] = pb[rr];
    }
    __syncthreads();

    int buf = 0;
#pragma unroll
    for (int kt = 0; kt < 16; kt++) {
        const int k0n = (kt + 1) * 16;
        if (kt < 15) {
#pragma unroll
            for (int rr = 0; rr < 2; rr++) {
                pa[rr] = *(const float4*)&Ab[(size_t)(o0 + ra + rr * 64) * 256 + k0n + ca];
                pb[rr] = *(const float4*)&Bb[(size_t)(k0n + rb + rr * 8) * N_ + n0 + cb];
            }
        }

#pragma unroll
        for (int kk = 0; kk < 16; kk++) {
            float af[8], bf[8];
            *(float4*)&af[0] = *(const float4*)&As[buf][kk][ty * 8 + 0];
            *(float4*)&af[4] = *(const float4*)&As[buf][kk][ty * 8 + 4];
            *(float4*)&bf[0] = *(const float4*)&Bs[buf][kk][tx * 8 + 0];
            *(float4*)&bf[4] = *(const float4*)&Bs[buf][kk][tx * 8 + 4];
#pragma unroll
            for (int i = 0; i < 8; i++)
#pragma unroll
                for (int j = 0; j < 8; j++)
                    acc[i][j] += af[i] * bf[j];
        }

        if (kt < 15) {
            const int nb = buf ^ 1;
#pragma unroll
            for (int rr = 0; rr < 2; rr++) {
                As[nb][ca + 0][ra + rr * 64] = pa[rr].x;
                As[nb][ca + 1][ra + rr * 64] = pa[rr].y;
                As[nb][ca + 2][ra + rr * 64] = pa[rr].z;
                As[nb][ca + 3][ra + rr * 64] = pa[rr].w;
                *(float4*)&Bs[nb][rb + rr * 8][cb] = pb[rr];
            }
            __syncthreads();
            buf = nb;
        }
    }

#pragma unroll
    for (int i = 0; i < 8; i++) {
        const int o = o0 + ty * 8 + i;
        const float sc = gamma[o] * rsqrtf(var[o] + EPS_);
        const float sh = beta[o] - mean[o] * sc;
        float4 v0, v1;
        v0.x = acc[i][0] * sc + sh; v0.y = acc[i][1] * sc + sh;
        v0.z = acc[i][2] * sc + sh; v0.w = acc[i][3] * sc + sh;
        v1.x = acc[i][4] * sc + sh; v1.y = acc[i][5] * sc + sh;
        v1.z = acc[i][6] * sc + sh; v1.w = acc[i][7] * sc + sh;
        float* po = &Ob[(size_t)o * N_ + n0 + tx * 8];
        *(float4*)&po[0] = v0;
        *(float4*)&po[4] = v1;
    }
}

// ---------------------------------------------------------------------------
__device__ __forceinline__ float blockReduceMax(float v) {
    __shared__ float sm[32];
#pragma unroll
    for (int o = 16; o; o >>= 1) v = fmaxf(v, __shfl_xor_sync(0xffffffffu, v, o));
    if ((threadIdx.x & 31) == 0) sm[threadIdx.x >> 5] = v;
    __syncthreads();
    if (threadIdx.x < 32) {
        float w = (threadIdx.x < (blockDim.x >> 5)) ? sm[threadIdx.x] : -CUDART_INF_F;
#pragma unroll
        for (int o = 16; o; o >>= 1) w = fmaxf(w, __shfl_xor_sync(0xffffffffu, w, o));
        if (threadIdx.x == 0) sm[0] = w;
    }
    __syncthreads();
    float r = sm[0];
    __syncthreads();
    return r;
}

__device__ __forceinline__ float blockReduceSum(float v) {
    __shared__ float sm[32];
#pragma unroll
    for (int o = 16; o; o >>= 1) v += __shfl_xor_sync(0xffffffffu, v, o);
    if ((threadIdx.x & 31) == 0) sm[threadIdx.x >> 5] = v;
    __syncthreads();
    if (threadIdx.x < 32) {
        float w = (threadIdx.x < (blockDim.x >> 5)) ? sm[threadIdx.x] : 0.f;
#pragma unroll
        for (int o = 16; o; o >>= 1) w += __shfl_xor_sync(0xffffffffu, w, o);
        if (threadIdx.x == 0) sm[0] = w;
    }
    __syncthreads();
    float r = sm[0];
    __syncthreads();
    return r;
}

// ---------------------------------------------------------------------------
__global__ __launch_bounds__(256)
void softmax_q()
{
    const int row = blockIdx.x;
    const int b = row >> 8;
    const int o = row & 255;
    float* p = g_qkv + (size_t)b * O3_ * N_ + (size_t)o * N_;
    const int t = threadIdx.x;

    float v[16];
#pragma unroll
    for (int i = 0; i < 16; i++) v[i] = p[t + i * 256];

    float m = -CUDART_INF_F;
#pragma unroll
    for (int i = 0; i < 16; i++) m = fmaxf(m, v[i]);
    m = blockReduceMax(m);

    float s = 0.f;
#pragma unroll
    for (int i = 0; i < 16; i++) { v[i] = __expf(v[i] - m); s += v[i]; }
    s = blockReduceSum(s);

    const float inv = 1.f / s;
#pragma unroll
    for (int i = 0; i < 16; i++) p[t + i * 256] = v[i] * inv;
}

// ---------------------------------------------------------------------------
// ctx split-N with fused k-softmax (atomic reduce into zeroed g_ctx)
// ---------------------------------------------------------------------------
__global__ __launch_bounds__(256)
void ctx_kernel()
{
    const int h = blockIdx.x;
    const int b = blockIdx.y;
    const int n0b = blockIdx.z * 256;
    const float* kp = g_qkv + (size_t)b * O3_ * N_ + (size_t)(C_ + h * HD_) * N_;
    const float* vp = g_qkv + (size_t)b * O3_ * N_ + (size_t)(2 * C_ + h * HD_) * N_;

    __shared__ float ks[128][33];
    __shared__ float vs[128][33];

    const int t = threadIdx.x;
    const int i = t >> 4;
    const int j = t & 15;
    float a00 = 0.f, a01 = 0.f, a10 = 0.f, a11 = 0.f;

    for (int cchunk = 0; cchunk < 2; cchunk++) {
        const int n0 = n0b + cchunk * 128;
#pragma unroll
        for (int s = 0; s < 16; s++) {
            const int l = t + s * 256;
            const int d = l >> 7, nn = l & 127;
            ks[nn][d] = kp[(size_t)d * N_ + n0 + nn];
            vs[nn][d] = vp[(size_t)d * N_ + n0 + nn];
        }
        __syncthreads();

        if (t < 128) {
            float m = -CUDART_INF_F;
#pragma unroll
            for (int d = 0; d < HD_; d++) m = fmaxf(m, ks[t][d]);
            float s = 0.f;
#pragma unroll
            for (int d = 0; d < HD_; d++) { float e = __expf(ks[t][d] - m); ks[t][d] = e; s += e; }
            const float inv = 1.f / s;
#pragma unroll
            for (int d = 0; d < HD_; d++) ks[t][d] *= inv;
        }
        __syncthreads();

#pragma unroll 8
        for (int kk = 0; kk < 128; kk++) {
            const float k0 = ks[kk][2 * i], k1 = ks[kk][2 * i + 1];
            const float v0 = vs[kk][2 * j], v1 = vs[kk][2 * j + 1];
            a00 += k0 * v0; a01 += k0 * v1;
            a10 += k1 * v0; a11 += k1 * v1;
        }
        __syncthreads();
    }

    float* cp = g_ctx + (size_t)((b * HEADS_ + h) * HD_) * HD_;
    atomicAdd(&cp[(2 * i + 0) * HD_ + 2 * j + 0], a00);
    atomicAdd(&cp[(2 * i + 0) * HD_ + 2 * j + 1], a01);
    atomicAdd(&cp[(2 * i + 1) * HD_ + 2 * j + 0], a10);
    atomicAdd(&cp[(2 * i + 1) * HD_ + 2 * j + 1], a11);
}

// ---------------------------------------------------------------------------
// fold v2: M[b,o,h*32+d] = sum_e proj_w[o,h*32+e] * ctx[b,h,d,e]
// grid (8 o-chunks of 32, B), block 256. ctx staged in smem transposed [h][e][d].
// ---------------------------------------------------------------------------
__global__ __launch_bounds__(256)
void fold_kernel(const float* __restrict__ pw)
{
    const int b  = blockIdx.y;
    const int o0 = blockIdx.x * 32;
    const int t  = threadIdx.x;

    __shared__ float ctxT[HEADS_][HD_][HD_ + 1];  // [h][e][d], padded
    __shared__ float pwr[256];

    const float* cb = g_ctx + (size_t)b * HEADS_ * HD_ * HD_;
#pragma unroll
    for (int s = 0; s < 32; s++) {
        const int idx = t + s * 256;          // h*1024 + d*32 + e
        const int h = idx >> 10;
        const int d = (idx >> 5) & 31;
        const int e = idx & 31;
        ctxT[h][e][d] = cb[idx];
    }
    __syncthreads();

    const int h = t >> 5, d = t & 31;
    float* Mb = g_M + ((size_t)b * C_ + o0) * C_;

    for (int oi = 0; oi < 32; oi++) {
        pwr[t] = pw[(size_t)(o0 + oi) * C_ + t];
        __syncthreads();
        float s = 0.f;
#pragma unroll
        for (int e = 0; e < HD_; e++)
            s += pwr[h * HD_ + e] * ctxT[h][e][d];
        Mb[(size_t)oi * C_ + t] = s;
        __syncthreads();
    }
}

// ---------------------------------------------------------------------------
extern "C" void kernel_launch(void* const* d_in, const int* in_sizes, int n_in,
                              void* d_out, int out_size)
{
    const float* x          = (const float*)d_in[0];
    const float* qkv_w      = (const float*)d_in[1];
    const float* qkv_gamma  = (const float*)d_in[2];
    const float* qkv_beta   = (const float*)d_in[3];
    const float* qkv_mean   = (const float*)d_in[4];
    const float* qkv_var    = (const float*)d_in[5];
    const float* proj_w     = (const float*)d_in[6];
    const float* proj_gamma = (const float*)d_in[7];
    const float* proj_beta  = (const float*)d_in[8];
    const float* proj_mean  = (const float*)d_in[9];
    const float* proj_var   = (const float*)d_in[10];
    float* out = (float*)d_out;

    void* p;
    cudaGetSymbolAddress(&p, g_qkv);
    float* qkv = (float*)p;
    cudaGetSymbolAddress(&p, g_M);
    float* Mm = (float*)p;
    void* ctxp;
    cudaGetSymbolAddress(&ctxp, g_ctx);

    gemm128_bn<<<dim3(N_ / 128, O3_ / 128, B_), 256>>>(
        qkv_w, 0, x, (long)C_ * N_, qkv, (long)O3_ * N_,
        qkv_gamma, qkv_beta, qkv_mean, qkv_var);

    softmax_q<<<B_ * C_, 256>>>();
    cudaMemsetAsync(ctxp, 0, sizeof(float) * B_ * HEADS_ * HD_ * HD_);

    ctx_kernel<<<dim3(HEADS_, B_, 16), 256>>>();

    fold_kernel<<<dim3(8, B_), 256>>>(proj_w);

    gemm128_bn<<<dim3(N_ / 128, C_ / 128, B_), 256>>>(
        Mm, (long)C_ * C_, qkv, (long)O3_ * N_, out, (long)C_ * N_,
        proj_gamma, proj_beta, proj_mean, proj_var);
}

// round 5
// speedup vs baseline: 2.1006x; 2.1006x over previous
#include <cuda_runtime.h>
#include <cstdint>
#include <math_constants.h>

#define B_   16
#define C_   256
#define N_   4096
#define O3_  768
#define HEADS_ 8
#define HD_  32
#define EPS_ 1e-5f

__device__ float g_qkv[(size_t)B_ * O3_ * N_];
__device__ float g_ctx[(size_t)B_ * HEADS_ * HD_ * HD_];
__device__ float g_M[(size_t)B_ * C_ * C_];

__device__ __forceinline__ uint32_t tf32c(float f) {
    uint32_t u;
    asm("cvt.rna.tf32.f32 %0, %1;" : "=r"(u) : "f"(f));
    return u;
}

__device__ __forceinline__ void mma_tf32(float* c, uint32_t a0, uint32_t a1,
                                         uint32_t a2, uint32_t a3,
                                         uint32_t b0, uint32_t b1) {
    asm volatile(
        "mma.sync.aligned.m16n8k8.row.col.f32.tf32.tf32.f32 "
        "{%0,%1,%2,%3}, {%4,%5,%6,%7}, {%8,%9}, {%0,%1,%2,%3};"
        : "+f"(c[0]), "+f"(c[1]), "+f"(c[2]), "+f"(c[3])
        : "r"(a0), "r"(a1), "r"(a2), "r"(a3), "r"(b0), "r"(b1));
}

// ---------------------------------------------------------------------------
// tf32 tensor-core GEMM, 128x128 tile, K=256, BN epilogue.
// C[o,n] = BN( sum_k A[o,k] * Bm[k,n] )  per batch (blockIdx.z)
// A row-major [M,256]; Bm row-major [256, N_] (k rows, n cols).
// 8 warps: warp_m = wid&3 (32 rows), warp_n = wid>>2 (64 cols).
// ---------------------------------------------------------------------------
__global__ __launch_bounds__(256)
void gemm_tc_bn(const float* __restrict__ A, long aStride,
                const float* __restrict__ Bm, long bStride,
                float* __restrict__ Out, long oStride,
                const float* __restrict__ gamma, const float* __restrict__ beta,
                const float* __restrict__ mean,  const float* __restrict__ var)
{
    const int b   = blockIdx.z;
    const int n0c = blockIdx.x * 128;
    const int o0c = blockIdx.y * 128;
    const float* Ab = A  + (size_t)b * aStride;
    const float* Bb = Bm + (size_t)b * bStride;
    float*       Ob = Out + (size_t)b * oStride;

    __shared__ uint32_t As[16][136];   // [k][o] tf32 bits, stride%32==8
    __shared__ uint32_t Bs[16][136];   // [k][n]

    const int t    = threadIdx.x;
    const int wid  = t >> 5;
    const int lane = t & 31;
    const int gid  = lane >> 2;
    const int tig  = lane & 3;
    const int m0   = (wid & 3) * 32;
    const int n0w  = (wid >> 2) * 64;

    float acc[2][8][4];
#pragma unroll
    for (int tm = 0; tm < 2; tm++)
#pragma unroll
        for (int tn = 0; tn < 8; tn++)
#pragma unroll
            for (int q = 0; q < 4; q++) acc[tm][tn][q] = 0.f;

    const int ra = t >> 2;            // 0..63
    const int ca = (t & 3) * 4;       // 0,4,8,12
    const int rb = t >> 5;            // 0..7
    const int cb = (t & 31) * 4;      // 0..124

    for (int k0 = 0; k0 < 256; k0 += 16) {
        // A tile: transpose [o][k] -> As[k][o], convert to tf32
#pragma unroll
        for (int rr = 0; rr < 2; rr++) {
            float4 av = *(const float4*)&Ab[(size_t)(o0c + ra + rr * 64) * 256 + k0 + ca];
            As[ca + 0][ra + rr * 64] = tf32c(av.x);
            As[ca + 1][ra + rr * 64] = tf32c(av.y);
            As[ca + 2][ra + rr * 64] = tf32c(av.z);
            As[ca + 3][ra + rr * 64] = tf32c(av.w);
        }
        // B tile: [k][n] direct, convert
#pragma unroll
        for (int rr = 0; rr < 2; rr++) {
            float4 bv = *(const float4*)&Bb[(size_t)(k0 + rb + rr * 8) * N_ + n0c + cb];
            uint4 u;
            u.x = tf32c(bv.x); u.y = tf32c(bv.y); u.z = tf32c(bv.z); u.w = tf32c(bv.w);
            *(uint4*)&Bs[rb + rr * 8][cb] = u;
        }
        __syncthreads();

#pragma unroll
        for (int ks = 0; ks < 2; ks++) {
            const int kb = ks * 8;
            uint32_t bf[8][2];
#pragma unroll
            for (int tn = 0; tn < 8; tn++) {
                bf[tn][0] = Bs[kb + tig][n0w + tn * 8 + gid];
                bf[tn][1] = Bs[kb + tig + 4][n0w + tn * 8 + gid];
            }
#pragma unroll
            for (int tm = 0; tm < 2; tm++) {
                const uint32_t a0 = As[kb + tig][m0 + tm * 16 + gid];
                const uint32_t a1 = As[kb + tig][m0 + tm * 16 + gid + 8];
                const uint32_t a2 = As[kb + tig + 4][m0 + tm * 16 + gid];
                const uint32_t a3 = As[kb + tig + 4][m0 + tm * 16 + gid + 8];
#pragma unroll
                for (int tn = 0; tn < 8; tn++)
                    mma_tf32(acc[tm][tn], a0, a1, a2, a3, bf[tn][0], bf[tn][1]);
            }
        }
        __syncthreads();
    }

    // BN epilogue: lane owns rows r0 = m0+tm*16+gid and r0+8, cols n0w+tn*8+2*tig(+1)
#pragma unroll
    for (int tm = 0; tm < 2; tm++) {
        const int o_a = o0c + m0 + tm * 16 + gid;
        const int o_b = o_a + 8;
        const float sc_a = gamma[o_a] * rsqrtf(var[o_a] + EPS_);
        const float sh_a = beta[o_a] - mean[o_a] * sc_a;
        const float sc_b = gamma[o_b] * rsqrtf(var[o_b] + EPS_);
        const float sh_b = beta[o_b] - mean[o_b] * sc_b;
#pragma unroll
        for (int tn = 0; tn < 8; tn++) {
            const int n = n0c + n0w + tn * 8 + 2 * tig;
            float2 va, vb;
            va.x = acc[tm][tn][0] * sc_a + sh_a;
            va.y = acc[tm][tn][1] * sc_a + sh_a;
            vb.x = acc[tm][tn][2] * sc_b + sh_b;
            vb.y = acc[tm][tn][3] * sc_b + sh_b;
            *(float2*)&Ob[(size_t)o_a * N_ + n] = va;
            *(float2*)&Ob[(size_t)o_b * N_ + n] = vb;
        }
    }
}

// ---------------------------------------------------------------------------
__device__ __forceinline__ float blockReduceMax(float v) {
    __shared__ float sm[32];
#pragma unroll
    for (int o = 16; o; o >>= 1) v = fmaxf(v, __shfl_xor_sync(0xffffffffu, v, o));
    if ((threadIdx.x & 31) == 0) sm[threadIdx.x >> 5] = v;
    __syncthreads();
    if (threadIdx.x < 32) {
        float w = (threadIdx.x < (blockDim.x >> 5)) ? sm[threadIdx.x] : -CUDART_INF_F;
#pragma unroll
        for (int o = 16; o; o >>= 1) w = fmaxf(w, __shfl_xor_sync(0xffffffffu, w, o));
        if (threadIdx.x == 0) sm[0] = w;
    }
    __syncthreads();
    float r = sm[0];
    __syncthreads();
    return r;
}

__device__ __forceinline__ float blockReduceSum(float v) {
    __shared__ float sm[32];
#pragma unroll
    for (int o = 16; o; o >>= 1) v += __shfl_xor_sync(0xffffffffu, v, o);
    if ((threadIdx.x & 31) == 0) sm[threadIdx.x >> 5] = v;
    __syncthreads();
    if (threadIdx.x < 32) {
        float w = (threadIdx.x < (blockDim.x >> 5)) ? sm[threadIdx.x] : 0.f;
#pragma unroll
        for (int o = 16; o; o >>= 1) w += __shfl_xor_sync(0xffffffffu, w, o);
        if (threadIdx.x == 0) sm[0] = w;
    }
    __syncthreads();
    float r = sm[0];
    __syncthreads();
    return r;
}

// ---------------------------------------------------------------------------
__global__ __launch_bounds__(256)
void softmax_q()
{
    const int row = blockIdx.x;
    const int b = row >> 8;
    const int o = row & 255;
    float* p = g_qkv + (size_t)b * O3_ * N_ + (size_t)o * N_;
    const int t = threadIdx.x;

    float v[16];
#pragma unroll
    for (int i = 0; i < 16; i++) v[i] = p[t + i * 256];

    float m = -CUDART_INF_F;
#pragma unroll
    for (int i = 0; i < 16; i++) m = fmaxf(m, v[i]);
    m = blockReduceMax(m);

    float s = 0.f;
#pragma unroll
    for (int i = 0; i < 16; i++) { v[i] = __expf(v[i] - m); s += v[i]; }
    s = blockReduceSum(s);

    const float inv = 1.f / s;
#pragma unroll
    for (int i = 0; i < 16; i++) p[t + i * 256] = v[i] * inv;
}

// ---------------------------------------------------------------------------
// ctx split-N with fused k-softmax (atomic reduce into zeroed g_ctx)
// ---------------------------------------------------------------------------
__global__ __launch_bounds__(256)
void ctx_kernel()
{
    const int h = blockIdx.x;
    const int b = blockIdx.y;
    const int n0b = blockIdx.z * 256;
    const float* kp = g_qkv + (size_t)b * O3_ * N_ + (size_t)(C_ + h * HD_) * N_;
    const float* vp = g_qkv + (size_t)b * O3_ * N_ + (size_t)(2 * C_ + h * HD_) * N_;

    __shared__ float ks[128][33];
    __shared__ float vs[128][33];

    const int t = threadIdx.x;
    const int i = t >> 4;
    const int j = t & 15;
    float a00 = 0.f, a01 = 0.f, a10 = 0.f, a11 = 0.f;

    for (int cchunk = 0; cchunk < 2; cchunk++) {
        const int n0 = n0b + cchunk * 128;
#pragma unroll
        for (int s = 0; s < 16; s++) {
            const int l = t + s * 256;
            const int d = l >> 7, nn = l & 127;
            ks[nn][d] = kp[(size_t)d * N_ + n0 + nn];
            vs[nn][d] = vp[(size_t)d * N_ + n0 + nn];
        }
        __syncthreads();

        if (t < 128) {
            float m = -CUDART_INF_F;
#pragma unroll
            for (int d = 0; d < HD_; d++) m = fmaxf(m, ks[t][d]);
            float s = 0.f;
#pragma unroll
            for (int d = 0; d < HD_; d++) { float e = __expf(ks[t][d] - m); ks[t][d] = e; s += e; }
            const float inv = 1.f / s;
#pragma unroll
            for (int d = 0; d < HD_; d++) ks[t][d] *= inv;
        }
        __syncthreads();

#pragma unroll 8
        for (int kk = 0; kk < 128; kk++) {
            const float k0 = ks[kk][2 * i], k1 = ks[kk][2 * i + 1];
            const float v0 = vs[kk][2 * j], v1 = vs[kk][2 * j + 1];
            a00 += k0 * v0; a01 += k0 * v1;
            a10 += k1 * v0; a11 += k1 * v1;
        }
        __syncthreads();
    }

    float* cp = g_ctx + (size_t)((b * HEADS_ + h) * HD_) * HD_;
    atomicAdd(&cp[(2 * i + 0) * HD_ + 2 * j + 0], a00);
    atomicAdd(&cp[(2 * i + 0) * HD_ + 2 * j + 1], a01);
    atomicAdd(&cp[(2 * i + 1) * HD_ + 2 * j + 0], a10);
    atomicAdd(&cp[(2 * i + 1) * HD_ + 2 * j + 1], a11);
}

// ---------------------------------------------------------------------------
// fold: M[b,o,h*32+d] = sum_e proj_w[o,h*32+e] * ctx[b,h,d,e]
// ---------------------------------------------------------------------------
__global__ __launch_bounds__(256)
void fold_kernel(const float* __restrict__ pw)
{
    const int b  = blockIdx.y;
    const int o0 = blockIdx.x * 32;
    const int t  = threadIdx.x;

    __shared__ float ctxT[HEADS_][HD_][HD_ + 1];
    __shared__ float pwr[256];

    const float* cb = g_ctx + (size_t)b * HEADS_ * HD_ * HD_;
#pragma unroll
    for (int s = 0; s < 32; s++) {
        const int idx = t + s * 256;
        const int h = idx >> 10;
        const int d = (idx >> 5) & 31;
        const int e = idx & 31;
        ctxT[h][e][d] = cb[idx];
    }
    __syncthreads();

    const int h = t >> 5, d = t & 31;
    float* Mb = g_M + ((size_t)b * C_ + o0) * C_;

    for (int oi = 0; oi < 32; oi++) {
        pwr[t] = pw[(size_t)(o0 + oi) * C_ + t];
        __syncthreads();
        float s = 0.f;
#pragma unroll
        for (int e = 0; e < HD_; e++)
            s += pwr[h * HD_ + e] * ctxT[h][e][d];
        Mb[(size_t)oi * C_ + t] = s;
        __syncthreads();
    }
}

// ---------------------------------------------------------------------------
extern "C" void kernel_launch(void* const* d_in, const int* in_sizes, int n_in,
                              void* d_out, int out_size)
{
    const float* x          = (const float*)d_in[0];
    const float* qkv_w      = (const float*)d_in[1];
    const float* qkv_gamma  = (const float*)d_in[2];
    const float* qkv_beta   = (const float*)d_in[3];
    const float* qkv_mean   = (const float*)d_in[4];
    const float* qkv_var    = (const float*)d_in[5];
    const float* proj_w     = (const float*)d_in[6];
    const float* proj_gamma = (const float*)d_in[7];
    const float* proj_beta  = (const float*)d_in[8];
    const float* proj_mean  = (const float*)d_in[9];
    const float* proj_var   = (const float*)d_in[10];
    float* out = (float*)d_out;

    void* p;
    cudaGetSymbolAddress(&p, g_qkv);
    float* qkv = (float*)p;
    cudaGetSymbolAddress(&p, g_M);
    float* Mm = (float*)p;
    void* ctxp;
    cudaGetSymbolAddress(&ctxp, g_ctx);

    // 1) QKV GEMM (tf32 mma) + BN -> g_qkv [b][768][4096]
    gemm_tc_bn<<<dim3(N_ / 128, O3_ / 128, B_), 256>>>(
        qkv_w, 0, x, (long)C_ * N_, qkv, (long)O3_ * N_,
        qkv_gamma, qkv_beta, qkv_mean, qkv_var);

    // 2) q softmax in place; zero ctx accumulator
    softmax_q<<<B_ * C_, 256>>>();
    cudaMemsetAsync(ctxp, 0, sizeof(float) * B_ * HEADS_ * HD_ * HD_);

    // 3) ctx = softmax_d(k) @ v^T
    ctx_kernel<<<dim3(HEADS_, B_, 16), 256>>>();

    // 4) fold proj_w with ctx
    fold_kernel<<<dim3(8, B_), 256>>>(proj_w);

    // 5) out = M @ q (tf32 mma) + proj BN
    gemm_tc_bn<<<dim3(N_ / 128, C_ / 128, B_), 256>>>(
        Mm, (long)C_ * C_, qkv, (long)O3_ * N_, out, (long)C_ * N_,
        proj_gamma, proj_beta, proj_mean, proj_var);
}

// round 6
// speedup vs baseline: 2.3468x; 1.1172x over previous
#include <cuda_runtime.h>
#include <cstdint>
#include <math_constants.h>

#define B_   16
#define C_   256
#define N_   4096
#define O3_  768
#define HEADS_ 8
#define HD_  32
#define EPS_ 1e-5f

__device__ float g_qkv[(size_t)B_ * O3_ * N_];   // q channels hold exp(BN(q))
__device__ float g_ctx[(size_t)B_ * HEADS_ * HD_ * HD_];
__device__ float g_M[(size_t)B_ * C_ * C_];      // proj_w @ ctx, col-scaled by 1/s_c
__device__ float g_ssum[(size_t)B_ * C_];        // s_c = sum_n exp(q[c,n])

__device__ __forceinline__ uint32_t tf32c(float f) {
    uint32_t u;
    asm("cvt.rna.tf32.f32 %0, %1;" : "=r"(u) : "f"(f));
    return u;
}

__device__ __forceinline__ void mma_tf32(float* c, uint32_t a0, uint32_t a1,
                                         uint32_t a2, uint32_t a3,
                                         uint32_t b0, uint32_t b1) {
    asm volatile(
        "mma.sync.aligned.m16n8k8.row.col.f32.tf32.tf32.f32 "
        "{%0,%1,%2,%3}, {%4,%5,%6,%7}, {%8,%9}, {%0,%1,%2,%3};"
        : "+f"(c[0]), "+f"(c[1]), "+f"(c[2]), "+f"(c[3])
        : "r"(a0), "r"(a1), "r"(a2), "r"(a3), "r"(b0), "r"(b1));
}

// ---------------------------------------------------------------------------
// tf32 tensor-core GEMM, 128x128 tile, K=256, BN epilogue.
// C[o,n] = BN( sum_k A[o,k] * Bm[k,n] )  per batch (blockIdx.z)
// If expq && o-tile is a q-tile (o<256): store exp(BN(.)) and atomically
// accumulate per-channel sums into ssum.
// ---------------------------------------------------------------------------
__global__ __launch_bounds__(256)
void gemm_tc_bn(const float* __restrict__ A, long aStride,
                const float* __restrict__ Bm, long bStride,
                float* __restrict__ Out, long oStride,
                const float* __restrict__ gamma, const float* __restrict__ beta,
                const float* __restrict__ mean,  const float* __restrict__ var,
                int expq, float* __restrict__ ssum)
{
    const int b   = blockIdx.z;
    const int n0c = blockIdx.x * 128;
    const int o0c = blockIdx.y * 128;
    const float* Ab = A  + (size_t)b * aStride;
    const float* Bb = Bm + (size_t)b * bStride;
    float*       Ob = Out + (size_t)b * oStride;

    __shared__ uint32_t As[16][136];   // [k][o] tf32 bits, stride%32==8
    __shared__ uint32_t Bs[16][136];   // [k][n]

    const int t    = threadIdx.x;
    const int wid  = t >> 5;
    const int lane = t & 31;
    const int gid  = lane >> 2;
    const int tig  = lane & 3;
    const int m0   = (wid & 3) * 32;
    const int n0w  = (wid >> 2) * 64;

    float acc[2][8][4];
#pragma unroll
    for (int tm = 0; tm < 2; tm++)
#pragma unroll
        for (int tn = 0; tn < 8; tn++)
#pragma unroll
            for (int q = 0; q < 4; q++) acc[tm][tn][q] = 0.f;

    const int ra = t >> 2;            // 0..63
    const int ca = (t & 3) * 4;       // 0,4,8,12
    const int rb = t >> 5;            // 0..7
    const int cb = (t & 31) * 4;      // 0..124

    for (int k0 = 0; k0 < 256; k0 += 16) {
#pragma unroll
        for (int rr = 0; rr < 2; rr++) {
            float4 av = *(const float4*)&Ab[(size_t)(o0c + ra + rr * 64) * 256 + k0 + ca];
            As[ca + 0][ra + rr * 64] = tf32c(av.x);
            As[ca + 1][ra + rr * 64] = tf32c(av.y);
            As[ca + 2][ra + rr * 64] = tf32c(av.z);
            As[ca + 3][ra + rr * 64] = tf32c(av.w);
        }
#pragma unroll
        for (int rr = 0; rr < 2; rr++) {
            float4 bv = *(const float4*)&Bb[(size_t)(k0 + rb + rr * 8) * N_ + n0c + cb];
            uint4 u;
            u.x = tf32c(bv.x); u.y = tf32c(bv.y); u.z = tf32c(bv.z); u.w = tf32c(bv.w);
            *(uint4*)&Bs[rb + rr * 8][cb] = u;
        }
        __syncthreads();

#pragma unroll
        for (int ks = 0; ks < 2; ks++) {
            const int kb = ks * 8;
            uint32_t bf[8][2];
#pragma unroll
            for (int tn = 0; tn < 8; tn++) {
                bf[tn][0] = Bs[kb + tig][n0w + tn * 8 + gid];
                bf[tn][1] = Bs[kb + tig + 4][n0w + tn * 8 + gid];
            }
#pragma unroll
            for (int tm = 0; tm < 2; tm++) {
                const uint32_t a0 = As[kb + tig][m0 + tm * 16 + gid];
                const uint32_t a1 = As[kb + tig][m0 + tm * 16 + gid + 8];
                const uint32_t a2 = As[kb + tig + 4][m0 + tm * 16 + gid];
                const uint32_t a3 = As[kb + tig + 4][m0 + tm * 16 + gid + 8];
#pragma unroll
                for (int tn = 0; tn < 8; tn++)
                    mma_tf32(acc[tm][tn], a0, a1, a2, a3, bf[tn][0], bf[tn][1]);
            }
        }
        __syncthreads();
    }

    const int doexp = expq && (o0c < 256);

#pragma unroll
    for (int tm = 0; tm < 2; tm++) {
        const int o_a = o0c + m0 + tm * 16 + gid;
        const int o_b = o_a + 8;
        const float sc_a = gamma[o_a] * rsqrtf(var[o_a] + EPS_);
        const float sh_a = beta[o_a] - mean[o_a] * sc_a;
        const float sc_b = gamma[o_b] * rsqrtf(var[o_b] + EPS_);
        const float sh_b = beta[o_b] - mean[o_b] * sc_b;
        float rs_a = 0.f, rs_b = 0.f;
#pragma unroll
        for (int tn = 0; tn < 8; tn++) {
            const int n = n0c + n0w + tn * 8 + 2 * tig;
            float2 va, vb;
            va.x = acc[tm][tn][0] * sc_a + sh_a;
            va.y = acc[tm][tn][1] * sc_a + sh_a;
            vb.x = acc[tm][tn][2] * sc_b + sh_b;
            vb.y = acc[tm][tn][3] * sc_b + sh_b;
            if (doexp) {
                va.x = __expf(va.x); va.y = __expf(va.y);
                vb.x = __expf(vb.x); vb.y = __expf(vb.y);
                rs_a += va.x + va.y;
                rs_b += vb.x + vb.y;
            }
            *(float2*)&Ob[(size_t)o_a * N_ + n] = va;
            *(float2*)&Ob[(size_t)o_b * N_ + n] = vb;
        }
        if (doexp) {
            // reduce across the 4 tig lanes (same gid)
            rs_a += __shfl_xor_sync(0xffffffffu, rs_a, 1);
            rs_a += __shfl_xor_sync(0xffffffffu, rs_a, 2);
            rs_b += __shfl_xor_sync(0xffffffffu, rs_b, 1);
            rs_b += __shfl_xor_sync(0xffffffffu, rs_b, 2);
            if (tig == 0) {
                atomicAdd(&ssum[b * C_ + o_a], rs_a);
                atomicAdd(&ssum[b * C_ + o_b], rs_b);
            }
        }
    }
}

// ---------------------------------------------------------------------------
// ctx split-N with fused k-softmax (atomic reduce into zeroed g_ctx)
// ---------------------------------------------------------------------------
__global__ __launch_bounds__(256)
void ctx_kernel()
{
    const int h = blockIdx.x;
    const int b = blockIdx.y;
    const int n0b = blockIdx.z * 256;
    const float* kp = g_qkv + (size_t)b * O3_ * N_ + (size_t)(C_ + h * HD_) * N_;
    const float* vp = g_qkv + (size_t)b * O3_ * N_ + (size_t)(2 * C_ + h * HD_) * N_;

    __shared__ float ks[128][33];
    __shared__ float vs[128][33];

    const int t = threadIdx.x;
    const int i = t >> 4;
    const int j = t & 15;
    float a00 = 0.f, a01 = 0.f, a10 = 0.f, a11 = 0.f;

    for (int cchunk = 0; cchunk < 2; cchunk++) {
        const int n0 = n0b + cchunk * 128;
#pragma unroll
        for (int s = 0; s < 16; s++) {
            const int l = t + s * 256;
            const int d = l >> 7, nn = l & 127;
            ks[nn][d] = kp[(size_t)d * N_ + n0 + nn];
            vs[nn][d] = vp[(size_t)d * N_ + n0 + nn];
        }
        __syncthreads();

        if (t < 128) {
            float m = -CUDART_INF_F;
#pragma unroll
            for (int d = 0; d < HD_; d++) m = fmaxf(m, ks[t][d]);
            float s = 0.f;
#pragma unroll
            for (int d = 0; d < HD_; d++) { float e = __expf(ks[t][d] - m); ks[t][d] = e; s += e; }
            const float inv = 1.f / s;
#pragma unroll
            for (int d = 0; d < HD_; d++) ks[t][d] *= inv;
        }
        __syncthreads();

#pragma unroll 8
        for (int kk = 0; kk < 128; kk++) {
            const float k0 = ks[kk][2 * i], k1 = ks[kk][2 * i + 1];
            const float v0 = vs[kk][2 * j], v1 = vs[kk][2 * j + 1];
            a00 += k0 * v0; a01 += k0 * v1;
            a10 += k1 * v0; a11 += k1 * v1;
        }
        __syncthreads();
    }

    float* cp = g_ctx + (size_t)((b * HEADS_ + h) * HD_) * HD_;
    atomicAdd(&cp[(2 * i + 0) * HD_ + 2 * j + 0], a00);
    atomicAdd(&cp[(2 * i + 0) * HD_ + 2 * j + 1], a01);
    atomicAdd(&cp[(2 * i + 1) * HD_ + 2 * j + 0], a10);
    atomicAdd(&cp[(2 * i + 1) * HD_ + 2 * j + 1], a11);
}

// ---------------------------------------------------------------------------
// fold v3: M[b,o,c=h*32+d] = (1/s_c) * sum_e proj_w[o,h*32+e] * ctx[b,h,d,e]
// grid (8 o-chunks of 32, B), block 256. Dynamic smem: ctxT + pw tile.
// ---------------------------------------------------------------------------
extern __shared__ float fold_sm[];

__global__ __launch_bounds__(256)
void fold_kernel(const float* __restrict__ pw)
{
    const int b  = blockIdx.y;
    const int o0 = blockIdx.x * 32;
    const int t  = threadIdx.x;

    float* ctxT = fold_sm;                 // [h][e][d] padded: 8*32*33
    float* pws  = fold_sm + 8 * 32 * 33;   // [32][256]

    const float* cb = g_ctx + (size_t)b * HEADS_ * HD_ * HD_;
#pragma unroll
    for (int s = 0; s < 32; s++) {
        const int idx = t + s * 256;          // h*1024 + d*32 + e
        const int h = idx >> 10;
        const int d = (idx >> 5) & 31;
        const int e = idx & 31;
        ctxT[(h * 32 + e) * 33 + d] = cb[idx];
    }
#pragma unroll
    for (int oi = 0; oi < 32; oi++)
        pws[oi * 256 + t] = pw[(size_t)(o0 + oi) * C_ + t];
    __syncthreads();

    const int h = t >> 5, d = t & 31;
    const float invs = 1.f / g_ssum[b * C_ + t];
    const float* ct = &ctxT[h * 32 * 33 + d];
    float* Mb = g_M + ((size_t)b * C_ + o0) * C_;

#pragma unroll 4
    for (int oi = 0; oi < 32; oi++) {
        const float* pr = &pws[oi * 256 + h * HD_];
        float s = 0.f;
#pragma unroll
        for (int e = 0; e < HD_; e++)
            s += pr[e] * ct[e * 33];
        Mb[(size_t)oi * C_ + t] = s * invs;
    }
}

// ---------------------------------------------------------------------------
extern "C" void kernel_launch(void* const* d_in, const int* in_sizes, int n_in,
                              void* d_out, int out_size)
{
    const float* x          = (const float*)d_in[0];
    const float* qkv_w      = (const float*)d_in[1];
    const float* qkv_gamma  = (const float*)d_in[2];
    const float* qkv_beta   = (const float*)d_in[3];
    const float* qkv_mean   = (const float*)d_in[4];
    const float* qkv_var    = (const float*)d_in[5];
    const float* proj_w     = (const float*)d_in[6];
    const float* proj_gamma = (const float*)d_in[7];
    const float* proj_beta  = (const float*)d_in[8];
    const float* proj_mean  = (const float*)d_in[9];
    const float* proj_var   = (const float*)d_in[10];
    float* out = (float*)d_out;

    void* p;
    cudaGetSymbolAddress(&p, g_qkv);  float* qkv = (float*)p;
    cudaGetSymbolAddress(&p, g_M);    float* Mm = (float*)p;
    cudaGetSymbolAddress(&p, g_ctx);  void* ctxp = p;
    cudaGetSymbolAddress(&p, g_ssum); float* ssum = (float*)p;

    const int FOLD_SM = (8 * 32 * 33 + 32 * 256) * sizeof(float);  // ~66.8 KB
    static int fold_cfg = 0;
    if (!fold_cfg) {
        cudaFuncSetAttribute(fold_kernel, cudaFuncAttributeMaxDynamicSharedMemorySize, FOLD_SM);
        fold_cfg = 1;
    }

    // zero accumulators (ssum + ctx)
    cudaMemsetAsync(ctxp, 0, sizeof(float) * B_ * HEADS_ * HD_ * HD_);
    cudaMemsetAsync(ssum, 0, sizeof(float) * B_ * C_);

    // 1) QKV GEMM (tf32 mma) + BN; q-channels exp'd + ssum atomics
    gemm_tc_bn<<<dim3(N_ / 128, O3_ / 128, B_), 256>>>(
        qkv_w, 0, x, (long)C_ * N_, qkv, (long)O3_ * N_,
        qkv_gamma, qkv_beta, qkv_mean, qkv_var, 1, ssum);

    // 2) ctx = softmax_d(k) @ v^T
    ctx_kernel<<<dim3(HEADS_, B_, 16), 256>>>();

    // 3) fold proj_w with ctx, column-scaled by 1/s_c
    fold_kernel<<<dim3(8, B_), 256, FOLD_SM>>>(proj_w);

    // 4) out = M @ exp_q (tf32 mma) + proj BN
    gemm_tc_bn<<<dim3(N_ / 128, C_ / 128, B_), 256>>>(
        Mm, (long)C_ * C_, qkv, (long)O3_ * N_, out, (long)C_ * N_,
        proj_gamma, proj_beta, proj_mean, proj_var, 0, ssum);
}

// round 7
// speedup vs baseline: 2.8176x; 1.2006x over previous
#include <cuda_runtime.h>
#include <cstdint>
#include <math_constants.h>

#define B_   16
#define C_   256
#define N_   4096
#define O3_  768
#define HEADS_ 8
#define HD_  32
#define EPS_ 1e-5f

__device__ float g_qkv[(size_t)B_ * O3_ * N_];   // q channels hold exp(BN(q))
__device__ float g_ctx[(size_t)B_ * HEADS_ * HD_ * HD_];
__device__ float g_M[(size_t)B_ * C_ * C_];      // proj_w @ ctx, col-scaled by 1/s_c
__device__ float g_ssum[(size_t)B_ * C_];        // s_c = sum_n exp(q[c,n])

__device__ __forceinline__ uint32_t smem_u32(const void* p) {
    uint32_t a;
    asm("{ .reg .u64 t; cvta.to.shared.u64 t, %1; cvt.u32.u64 %0, t; }"
        : "=r"(a) : "l"(p));
    return a;
}

__device__ __forceinline__ void cp16(uint32_t dst, const void* src) {
    asm volatile("cp.async.cg.shared.global [%0], [%1], 16;" :: "r"(dst), "l"(src));
}
#define CP_COMMIT() asm volatile("cp.async.commit_group;" ::: "memory")
#define CP_WAIT0()  asm volatile("cp.async.wait_group 0;" ::: "memory")

__device__ __forceinline__ void mma_tf32(float* c, uint32_t a0, uint32_t a1,
                                         uint32_t a2, uint32_t a3,
                                         uint32_t b0, uint32_t b1) {
    asm volatile(
        "mma.sync.aligned.m16n8k8.row.col.f32.tf32.tf32.f32 "
        "{%0,%1,%2,%3}, {%4,%5,%6,%7}, {%8,%9}, {%0,%1,%2,%3};"
        : "+f"(c[0]), "+f"(c[1]), "+f"(c[2]), "+f"(c[3])
        : "r"(a0), "r"(a1), "r"(a2), "r"(a3), "r"(b0), "r"(b1));
}

#define APAD 20     // floats per A row (16 + 4 pad); 20*4=80B, 16B-aligned
#define BPAD 136    // floats per B row (128 + 8 pad); stride%32==8
#define ABUF (128 * APAD)
#define BBUF (16 * BPAD)

// ---------------------------------------------------------------------------
// tf32 tensor-core GEMM, 128x128 tile, K=256, cp.async double-buffered,
// BN epilogue. C[o,n] = BN( sum_k A[o,k] * Bm[k,n] )  per batch (blockIdx.z).
// expq: q-channel tiles store exp(BN(.)) and accumulate ssum.
// ---------------------------------------------------------------------------
__global__ __launch_bounds__(256)
void gemm_tc_bn(const float* __restrict__ A, long aStride,
                const float* __restrict__ Bm, long bStride,
                float* __restrict__ Out, long oStride,
                const float* __restrict__ gamma, const float* __restrict__ beta,
                const float* __restrict__ mean,  const float* __restrict__ var,
                int expq, float* __restrict__ ssum)
{
    const int b   = blockIdx.z;
    const int n0c = blockIdx.x * 128;
    const int o0c = blockIdx.y * 128;
    const float* Ab = A  + (size_t)b * aStride;
    const float* Bb = Bm + (size_t)b * bStride;
    float*       Ob = Out + (size_t)b * oStride;

    __shared__ float As[2][ABUF];   // [o][k] raw f32, pad 20
    __shared__ float Bs[2][BBUF];   // [k][n] raw f32, pad 136

    const int t    = threadIdx.x;
    const int wid  = t >> 5;
    const int lane = t & 31;
    const int gid  = lane >> 2;
    const int tig  = lane & 3;
    const int m0   = (wid & 3) * 32;
    const int n0w  = (wid >> 2) * 64;

    const uint32_t smA = smem_u32(&As[0][0]);
    const uint32_t smB = smem_u32(&Bs[0][0]);

    float acc[2][8][4];
#pragma unroll
    for (int tm = 0; tm < 2; tm++)
#pragma unroll
        for (int tn = 0; tn < 8; tn++)
#pragma unroll
            for (int q = 0; q < 4; q++) acc[tm][tn][q] = 0.f;

    // prefetch indices (2 A-chunks + 2 B-chunks of 16B per thread)
    const int aco = t >> 1;                 // c>>2 for c=t*2... use explicit below
    (void)aco;

    // ---- prefetch tile 0 ----
    {
        const int k0 = 0;
#pragma unroll
        for (int r = 0; r < 2; r++) {
            const int c = t + r * 256;
            const int o = c >> 2, kp = (c & 3) * 4;
            cp16(smA + (uint32_t)(o * APAD + kp) * 4,
                 Ab + (size_t)(o0c + o) * 256 + k0 + kp);
        }
#pragma unroll
        for (int r = 0; r < 2; r++) {
            const int c = t + r * 256;
            const int k = c >> 5, np = (c & 31) * 4;
            cp16(smB + (uint32_t)(k * BPAD + np) * 4,
                 Bb + (size_t)(k0 + k) * N_ + n0c + np);
        }
        CP_COMMIT();
    }

    for (int kt = 0; kt < 16; kt++) {
        CP_WAIT0();
        __syncthreads();

        if (kt < 15) {
            const int k0 = (kt + 1) * 16;
            const uint32_t bufo = (uint32_t)((kt + 1) & 1);
            const uint32_t dA = smA + bufo * (ABUF * 4);
            const uint32_t dB = smB + bufo * (BBUF * 4);
#pragma unroll
            for (int r = 0; r < 2; r++) {
                const int c = t + r * 256;
                const int o = c >> 2, kp = (c & 3) * 4;
                cp16(dA + (uint32_t)(o * APAD + kp) * 4,
                     Ab + (size_t)(o0c + o) * 256 + k0 + kp);
            }
#pragma unroll
            for (int r = 0; r < 2; r++) {
                const int c = t + r * 256;
                const int k = c >> 5, np = (c & 31) * 4;
                cp16(dB + (uint32_t)(k * BPAD + np) * 4,
                     Bb + (size_t)(k0 + k) * N_ + n0c + np);
            }
            CP_COMMIT();
        }

        const float* As2 = As[kt & 1];
        const float* Bs2 = Bs[kt & 1];

#pragma unroll
        for (int ks = 0; ks < 2; ks++) {
            const int kb = ks * 8;
            uint32_t bf[8][2];
#pragma unroll
            for (int tn = 0; tn < 8; tn++) {
                bf[tn][0] = __float_as_uint(Bs2[(kb + tig) * BPAD + n0w + tn * 8 + gid]);
                bf[tn][1] = __float_as_uint(Bs2[(kb + tig + 4) * BPAD + n0w + tn * 8 + gid]);
            }
#pragma unroll
            for (int tm = 0; tm < 2; tm++) {
                const int oa = (m0 + tm * 16 + gid) * APAD;
                const int ob = (m0 + tm * 16 + gid + 8) * APAD;
                const uint32_t a0 = __float_as_uint(As2[oa + kb + tig]);
                const uint32_t a1 = __float_as_uint(As2[ob + kb + tig]);
                const uint32_t a2 = __float_as_uint(As2[oa + kb + tig + 4]);
                const uint32_t a3 = __float_as_uint(As2[ob + kb + tig + 4]);
#pragma unroll
                for (int tn = 0; tn < 8; tn++)
                    mma_tf32(acc[tm][tn], a0, a1, a2, a3, bf[tn][0], bf[tn][1]);
            }
        }
        __syncthreads();
    }

    const int doexp = expq && (o0c < 256);

#pragma unroll
    for (int tm = 0; tm < 2; tm++) {
        const int o_a = o0c + m0 + tm * 16 + gid;
        const int o_b = o_a + 8;
        const float sc_a = gamma[o_a] * rsqrtf(var[o_a] + EPS_);
        const float sh_a = beta[o_a] - mean[o_a] * sc_a;
        const float sc_b = gamma[o_b] * rsqrtf(var[o_b] + EPS_);
        const float sh_b = beta[o_b] - mean[o_b] * sc_b;
        float rs_a = 0.f, rs_b = 0.f;
#pragma unroll
        for (int tn = 0; tn < 8; tn++) {
            const int n = n0c + n0w + tn * 8 + 2 * tig;
            float2 va, vb;
            va.x = acc[tm][tn][0] * sc_a + sh_a;
            va.y = acc[tm][tn][1] * sc_a + sh_a;
            vb.x = acc[tm][tn][2] * sc_b + sh_b;
            vb.y = acc[tm][tn][3] * sc_b + sh_b;
            if (doexp) {
                va.x = __expf(va.x); va.y = __expf(va.y);
                vb.x = __expf(vb.x); vb.y = __expf(vb.y);
                rs_a += va.x + va.y;
                rs_b += vb.x + vb.y;
            }
            *(float2*)&Ob[(size_t)o_a * N_ + n] = va;
            *(float2*)&Ob[(size_t)o_b * N_ + n] = vb;
        }
        if (doexp) {
            rs_a += __shfl_xor_sync(0xffffffffu, rs_a, 1);
            rs_a += __shfl_xor_sync(0xffffffffu, rs_a, 2);
            rs_b += __shfl_xor_sync(0xffffffffu, rs_b, 1);
            rs_b += __shfl_xor_sync(0xffffffffu, rs_b, 2);
            if (tig == 0) {
                atomicAdd(&ssum[b * C_ + o_a], rs_a);
                atomicAdd(&ssum[b * C_ + o_b], rs_b);
            }
        }
    }
}

// ---------------------------------------------------------------------------
// ctx split-N with fused k-softmax (atomic reduce into zeroed g_ctx)
// ---------------------------------------------------------------------------
__global__ __launch_bounds__(256)
void ctx_kernel()
{
    const int h = blockIdx.x;
    const int b = blockIdx.y;
    const int n0b = blockIdx.z * 256;
    const float* kp = g_qkv + (size_t)b * O3_ * N_ + (size_t)(C_ + h * HD_) * N_;
    const float* vp = g_qkv + (size_t)b * O3_ * N_ + (size_t)(2 * C_ + h * HD_) * N_;

    __shared__ float ks[128][33];
    __shared__ float vs[128][33];

    const int t = threadIdx.x;
    const int i = t >> 4;
    const int j = t & 15;
    float a00 = 0.f, a01 = 0.f, a10 = 0.f, a11 = 0.f;

    for (int cchunk = 0; cchunk < 2; cchunk++) {
        const int n0 = n0b + cchunk * 128;
#pragma unroll
        for (int s = 0; s < 16; s++) {
            const int l = t + s * 256;
            const int d = l >> 7, nn = l & 127;
            ks[nn][d] = kp[(size_t)d * N_ + n0 + nn];
            vs[nn][d] = vp[(size_t)d * N_ + n0 + nn];
        }
        __syncthreads();

        if (t < 128) {
            float m = -CUDART_INF_F;
#pragma unroll
            for (int d = 0; d < HD_; d++) m = fmaxf(m, ks[t][d]);
            float s = 0.f;
#pragma unroll
            for (int d = 0; d < HD_; d++) { float e = __expf(ks[t][d] - m); ks[t][d] = e; s += e; }
            const float inv = 1.f / s;
#pragma unroll
            for (int d = 0; d < HD_; d++) ks[t][d] *= inv;
        }
        __syncthreads();

#pragma unroll 8
        for (int kk = 0; kk < 128; kk++) {
            const float k0 = ks[kk][2 * i], k1 = ks[kk][2 * i + 1];
            const float v0 = vs[kk][2 * j], v1 = vs[kk][2 * j + 1];
            a00 += k0 * v0; a01 += k0 * v1;
            a10 += k1 * v0; a11 += k1 * v1;
        }
        __syncthreads();
    }

    float* cp = g_ctx + (size_t)((b * HEADS_ + h) * HD_) * HD_;
    atomicAdd(&cp[(2 * i + 0) * HD_ + 2 * j + 0], a00);
    atomicAdd(&cp[(2 * i + 0) * HD_ + 2 * j + 1], a01);
    atomicAdd(&cp[(2 * i + 1) * HD_ + 2 * j + 0], a10);
    atomicAdd(&cp[(2 * i + 1) * HD_ + 2 * j + 1], a11);
}

// ---------------------------------------------------------------------------
// fold v3: M[b,o,c=h*32+d] = (1/s_c) * sum_e proj_w[o,h*32+e] * ctx[b,h,d,e]
// ---------------------------------------------------------------------------
extern __shared__ float fold_sm[];

__global__ __launch_bounds__(256)
void fold_kernel(const float* __restrict__ pw)
{
    const int b  = blockIdx.y;
    const int o0 = blockIdx.x * 32;
    const int t  = threadIdx.x;

    float* ctxT = fold_sm;                 // [h][e][d] padded: 8*32*33
    float* pws  = fold_sm + 8 * 32 * 33;   // [32][256]

    const float* cb = g_ctx + (size_t)b * HEADS_ * HD_ * HD_;
#pragma unroll
    for (int s = 0; s < 32; s++) {
        const int idx = t + s * 256;          // h*1024 + d*32 + e
        const int h = idx >> 10;
        const int d = (idx >> 5) & 31;
        const int e = idx & 31;
        ctxT[(h * 32 + e) * 33 + d] = cb[idx];
    }
#pragma unroll
    for (int oi = 0; oi < 32; oi++)
        pws[oi * 256 + t] = pw[(size_t)(o0 + oi) * C_ + t];
    __syncthreads();

    const int h = t >> 5, d = t & 31;
    const float invs = 1.f / g_ssum[b * C_ + t];
    const float* ct = &ctxT[h * 32 * 33 + d];
    float* Mb = g_M + ((size_t)b * C_ + o0) * C_;

#pragma unroll 4
    for (int oi = 0; oi < 32; oi++) {
        const float* pr = &pws[oi * 256 + h * HD_];
        float s = 0.f;
#pragma unroll
        for (int e = 0; e < HD_; e++)
            s += pr[e] * ct[e * 33];
        Mb[(size_t)oi * C_ + t] = s * invs;
    }
}

// ---------------------------------------------------------------------------
extern "C" void kernel_launch(void* const* d_in, const int* in_sizes, int n_in,
                              void* d_out, int out_size)
{
    const float* x          = (const float*)d_in[0];
    const float* qkv_w      = (const float*)d_in[1];
    const float* qkv_gamma  = (const float*)d_in[2];
    const float* qkv_beta   = (const float*)d_in[3];
    const float* qkv_mean   = (const float*)d_in[4];
    const float* qkv_var    = (const float*)d_in[5];
    const float* proj_w     = (const float*)d_in[6];
    const float* proj_gamma = (const float*)d_in[7];
    const float* proj_beta  = (const float*)d_in[8];
    const float* proj_mean  = (const float*)d_in[9];
    const float* proj_var   = (const float*)d_in[10];
    float* out = (float*)d_out;

    void* p;
    cudaGetSymbolAddress(&p, g_qkv);  float* qkv = (float*)p;
    cudaGetSymbolAddress(&p, g_M);    float* Mm = (float*)p;
    cudaGetSymbolAddress(&p, g_ctx);  void* ctxp = p;
    cudaGetSymbolAddress(&p, g_ssum); float* ssum = (float*)p;

    const int FOLD_SM = (8 * 32 * 33 + 32 * 256) * sizeof(float);
    static int fold_cfg = 0;
    if (!fold_cfg) {
        cudaFuncSetAttribute(fold_kernel, cudaFuncAttributeMaxDynamicSharedMemorySize, FOLD_SM);
        fold_cfg = 1;
    }

    cudaMemsetAsync(ctxp, 0, sizeof(float) * B_ * HEADS_ * HD_ * HD_);
    cudaMemsetAsync(ssum, 0, sizeof(float) * B_ * C_);

    // 1) QKV GEMM (tf32 mma, cp.async) + BN; q-channels exp'd + ssum atomics
    gemm_tc_bn<<<dim3(N_ / 128, O3_ / 128, B_), 256>>>(
        qkv_w, 0, x, (long)C_ * N_, qkv, (long)O3_ * N_,
        qkv_gamma, qkv_beta, qkv_mean, qkv_var, 1, ssum);

    // 2) ctx = softmax_d(k) @ v^T
    ctx_kernel<<<dim3(HEADS_, B_, 16), 256>>>();

    // 3) fold proj_w with ctx, column-scaled by 1/s_c
    fold_kernel<<<dim3(8, B_), 256, FOLD_SM>>>(proj_w);

    // 4) out = M @ exp_q (tf32 mma, cp.async) + proj BN
    gemm_tc_bn<<<dim3(N_ / 128, C_ / 128, B_), 256>>>(
        Mm, (long)C_ * C_, qkv, (long)O3_ * N_, out, (long)C_ * N_,
        proj_gamma, proj_beta, proj_mean, proj_var, 0, ssum);
}